// round 8
// baseline (speedup 1.0000x reference)
#include <cuda_runtime.h>
#include <cuda_fp16.h>
#include <math.h>
#include <stdint.h>

#define NNODES 50000
#define NEDGES 800000
#define NTOK   100000
#define SEQLEN 32
#define EMBD   128
#define INFEAT 256
#define NHID   256
#define NCLS   40

#define CHUNK   512
#define NCHUNK  98      // 98*512 = 50176 >= 50000

typedef unsigned long long ull;

// ---------------- scratch (device globals; no allocation allowed) ------------
__device__ int   g_deg_out[NNODES];
__device__ int   g_deg_in[NNODES];
__device__ float g_norm_s[NNODES];
__device__ float g_norm_d[NNODES];
__device__ int   g_row_ptr[NNODES + 1];
__device__ int   g_cursor[NNODES];
__device__ int   g_chunk_sum[NCHUNK];
__device__ int   g_chunk_off[NCHUNK];
__device__ int   g_csr_src[NEDGES];
__device__ __align__(16) __half g_embh[(size_t)NTOK * EMBD];      // fp16 emb table
__device__ __align__(16) uint32_t g_w1t[NHID * INFEAT];           // W1^T [n][k] tf32 bits
__device__ __align__(16) __half g_hw1h[(size_t)NNODES * NHID];    // h@W1 fp16
__device__ float g_out1[(size_t)NNODES * NHID];                   // relu(agg*norm_d+b1)
__device__ __align__(16) __half g_hws2h[(size_t)NNODES * NCLS];   // (out1@W2)*norm_s fp16

// ---------------- helpers -----------------------------------------------------
__device__ __forceinline__ ull ffma2(ull a, ull b, ull c) {
    ull d;
    asm("fma.rn.f32x2 %0, %1, %2, %3;" : "=l"(d) : "l"(a), "l"(b), "l"(c));
    return d;
}
__device__ __forceinline__ ull dup2(float x) {
    ull d;
    asm("mov.b64 %0, {%1, %1};" : "=l"(d) : "f"(x));
    return d;
}
__device__ __forceinline__ void unpack2(ull v, float& lo, float& hi) {
    asm("mov.b64 {%0, %1}, %2;" : "=f"(lo), "=f"(hi) : "l"(v));
}
__device__ __forceinline__ uint32_t f2tf32(float f) {
    uint32_t u;
    asm("cvt.rna.tf32.f32 %0, %1;" : "=r"(u) : "f"(f));
    return u;
}
__device__ __forceinline__ void mma_tf32(float* c, const uint32_t* a, uint32_t b0, uint32_t b1) {
    asm volatile(
        "mma.sync.aligned.m16n8k8.row.col.f32.tf32.tf32.f32 "
        "{%0,%1,%2,%3}, {%4,%5,%6,%7}, {%8,%9}, {%0,%1,%2,%3};"
        : "+f"(c[0]), "+f"(c[1]), "+f"(c[2]), "+f"(c[3])
        : "r"(a[0]), "r"(a[1]), "r"(a[2]), "r"(a[3]), "r"(b0), "r"(b1));
}
__device__ __forceinline__ uint32_t smem_u32(const void* p) {
    uint32_t a;
    asm("{ .reg .u64 t; cvta.to.shared.u64 t, %1; cvt.u32.u64 %0, t; }" : "=r"(a) : "l"(p));
    return a;
}
__device__ __forceinline__ void cpa16(uint32_t dst, const void* src) {
    asm volatile("cp.async.cg.shared.global [%0], [%1], 16;" :: "r"(dst), "l"(src));
}
#define CPA_COMMIT() asm volatile("cp.async.commit_group;" ::: "memory")
#define CPA_WAIT0()  asm volatile("cp.async.wait_group 0;" ::: "memory")

// ---------------- emb table fp32 -> fp16 --------------------------------------
__global__ void conv_emb_kernel(const float* __restrict__ emb) {
    int i = blockIdx.x * blockDim.x + threadIdx.x;
    size_t base = (size_t)i * 8;
    if (base >= (size_t)NTOK * EMBD) return;
    float4 a = *(const float4*)&emb[base];
    float4 b = *(const float4*)&emb[base + 4];
    __half2 h0 = __float22half2_rn(make_float2(a.x, a.y));
    __half2 h1 = __float22half2_rn(make_float2(a.z, a.w));
    __half2 h2 = __float22half2_rn(make_float2(b.x, b.y));
    __half2 h3 = __float22half2_rn(make_float2(b.z, b.w));
    *(uint4*)&g_embh[base] = make_uint4(*(unsigned*)&h0, *(unsigned*)&h1,
                                        *(unsigned*)&h2, *(unsigned*)&h3);
}

// ---------------- degree ------------------------------------------------------
__global__ void zero_degs_kernel() {
    int i = blockIdx.x * blockDim.x + threadIdx.x;
    if (i < NNODES) { g_deg_out[i] = 0; g_deg_in[i] = 0; }
}

__global__ void degree_kernel(const int* __restrict__ src, const int* __restrict__ dst) {
    int e = blockIdx.x * blockDim.x + threadIdx.x;
    if (e < NEDGES) {
        atomicAdd(&g_deg_out[src[e]], 1);
        atomicAdd(&g_deg_in[dst[e]], 1);
    }
}

// ---------------- scan + norms ------------------------------------------------
__global__ void scanA_kernel() {
    __shared__ int s[CHUNK];
    int t = threadIdx.x, b = blockIdx.x;
    int idx = b * CHUNK + t;
    int v = (idx < NNODES) ? g_deg_in[idx] : 0;
    s[t] = v;
    __syncthreads();
    for (int off = CHUNK / 2; off > 0; off >>= 1) {
        if (t < off) s[t] += s[t + off];
        __syncthreads();
    }
    if (t == 0) g_chunk_sum[b] = s[0];
}

__global__ void scanB_kernel() {
    __shared__ int s[128];
    int t = threadIdx.x;
    int v = (t < NCHUNK) ? g_chunk_sum[t] : 0;
    s[t] = v;
    __syncthreads();
    for (int off = 1; off < 128; off <<= 1) {
        int x = (t >= off) ? s[t - off] : 0;
        __syncthreads();
        s[t] += x;
        __syncthreads();
    }
    if (t < NCHUNK) g_chunk_off[t] = s[t] - v;
    if (t == 0) g_row_ptr[NNODES] = NEDGES;
}

__global__ void scanC_kernel() {
    __shared__ int s[CHUNK];
    int t = threadIdx.x, b = blockIdx.x;
    int idx = b * CHUNK + t;
    int v = (idx < NNODES) ? g_deg_in[idx] : 0;
    s[t] = v;
    __syncthreads();
    for (int off = 1; off < CHUNK; off <<= 1) {
        int x = (t >= off) ? s[t - off] : 0;
        __syncthreads();
        s[t] += x;
        __syncthreads();
    }
    if (idx < NNODES) {
        int excl = g_chunk_off[b] + s[t] - v;
        g_row_ptr[idx] = excl;
        g_cursor[idx]  = excl;
        int dins = v; if (dins < 1) dins = 1;
        int dofs = g_deg_out[idx]; if (dofs < 1) dofs = 1;
        g_norm_d[idx] = rsqrtf((float)dins);
        g_norm_s[idx] = rsqrtf((float)dofs);
    }
}

__global__ void csr_fill_kernel(const int* __restrict__ src, const int* __restrict__ dst) {
    int e = blockIdx.x * blockDim.x + threadIdx.x;
    if (e < NEDGES) {
        int d = dst[e];
        int pos = atomicAdd(&g_cursor[d], 1);
        g_csr_src[pos] = src[e];
    }
}

// ---------------- prep W1: [K][N] fp32 -> [N][K] tf32 bits -------------------
__global__ void prep_w1_kernel(const float* __restrict__ W1) {
    int i = blockIdx.x * blockDim.x + threadIdx.x;   // 65536
    int n = i >> 8, k = i & 255;
    g_w1t[n * INFEAT + k] = f2tf32(W1[k * NHID + n]);
}

// ---------------- FUSED embed + GEMM1 ----------------------------------------
// CTA: 128 nodes x N=256, K=256. Phase 1: pool 128 rows into smem A (tf32).
// Phase 2: tf32 MMA, warp tile 32x128, B via cp.async 2-stage.
#define ASTRA 260                 // A row stride (words): 256 + 4 pad
#define BSTR  36                  // B row stride (words): 32 + 4 pad
#define A_WORDS (128 * ASTRA)     // 33280
#define BSTAGE_WORDS (256 * BSTR) // 9216
#define G1_SMEM ((A_WORDS + 2 * BSTAGE_WORDS) * 4)   // 206848 bytes

__global__ __launch_bounds__(256, 1)
void gemm1_fused_kernel(const int* __restrict__ feats) {
    extern __shared__ __align__(16) uint32_t smem[];
    uint32_t* As = smem;
    uint32_t* Bs = smem + A_WORDS;

    int tid = threadIdx.x, wid = tid >> 5, lane = tid & 31;
    int wm = wid & 3, wn = wid >> 2;
    int g = lane >> 2, tig = lane & 3;
    int bm = blockIdx.x * 128;

    uint32_t sbB = smem_u32(smem) + A_WORDS * 4;

    // --- issue B stage 0 (overlaps pooling) ---
    {
        int n = tid;   // 256 rows
        uint32_t dst = sbB + n * (BSTR * 4);
        const uint32_t* src = &g_w1t[n * INFEAT];
#pragma unroll
        for (int c = 0; c < 8; c++) cpa16(dst + c * 16, src + c * 4);
        CPA_COMMIT();
    }

    // --- phase 1: pooling, warp per node, 16 nodes per warp ---
    for (int pass = 0; pass < 16; pass++) {
        int nl = wid * 16 + pass;
        int node = bm + nl;
        float4 h1 = make_float4(0.f, 0.f, 0.f, 0.f);
        float4 mx = make_float4(0.f, 0.f, 0.f, 0.f);
        if (node < NNODES) {
            int tok = feats[node * SEQLEN + lane];
            int cnt = __popc(__ballot_sync(0xffffffffu, tok != 0));
            if (cnt < 1) cnt = 1;
            float4 s = make_float4(0.f, 0.f, 0.f, 0.f);
            mx = make_float4(-INFINITY, -INFINITY, -INFINITY, -INFINITY);
#pragma unroll
            for (int t = 0; t < 32; t++) {
                int tk = __shfl_sync(0xffffffffu, tok, t);
                float4 v = make_float4(0.f, 0.f, 0.f, 0.f);
                if (tk != 0) {
                    uint2 u = *(const uint2*)&g_embh[(size_t)tk * EMBD + lane * 4];
                    float2 f0 = __half22float2(*(const __half2*)&u.x);
                    float2 f1 = __half22float2(*(const __half2*)&u.y);
                    v = make_float4(f0.x, f0.y, f1.x, f1.y);
                }
                s.x += v.x; s.y += v.y; s.z += v.z; s.w += v.w;
                mx.x = fmaxf(mx.x, v.x); mx.y = fmaxf(mx.y, v.y);
                mx.z = fmaxf(mx.z, v.z); mx.w = fmaxf(mx.w, v.w);
            }
            float inv = 1.0f / (float)cnt;
            h1 = make_float4(s.x * inv, s.y * inv, s.z * inv, s.w * inv);
        }
        uint32_t* a0 = &As[nl * ASTRA + lane * 4];
        a0[0] = f2tf32(h1.x); a0[1] = f2tf32(h1.y);
        a0[2] = f2tf32(h1.z); a0[3] = f2tf32(h1.w);
        uint32_t* a1 = a0 + EMBD;
        a1[0] = f2tf32(mx.x); a1[1] = f2tf32(mx.y);
        a1[2] = f2tf32(mx.z); a1[3] = f2tf32(mx.w);
    }

    float acc[2][16][4];
#pragma unroll
    for (int mi = 0; mi < 2; mi++)
#pragma unroll
        for (int ni = 0; ni < 16; ni++)
#pragma unroll
            for (int q = 0; q < 4; q++) acc[mi][ni][q] = 0.f;

    __syncthreads();   // As complete

    // --- phase 2: MMA over 8 K-chunks of 32 ---
    const int NKC = INFEAT / 32;   // 8
    for (int kc = 0; kc < NKC; kc++) {
        CPA_WAIT0();               // stage kc resident
        __syncthreads();           // all warps done with buffer being overwritten
        if (kc + 1 < NKC) {        // issue stage kc+1 into other buffer
            int n = tid;
            uint32_t dst = sbB + ((kc + 1) & 1) * (BSTAGE_WORDS * 4) + n * (BSTR * 4);
            const uint32_t* src = &g_w1t[n * INFEAT + (kc + 1) * 32];
#pragma unroll
            for (int c = 0; c < 8; c++) cpa16(dst + c * 16, src + c * 4);
            CPA_COMMIT();
        }

        const uint32_t* Bc = Bs + (kc & 1) * BSTAGE_WORDS;
#pragma unroll
        for (int ks = 0; ks < 4; ks++) {
            int ka = kc * 32 + ks * 8 + tig;   // A k index
            int kb = ks * 8 + tig;             // B k index (within stage)
            uint32_t af[2][4];
#pragma unroll
            for (int mi = 0; mi < 2; mi++) {
                int r = wm * 32 + mi * 16 + g;
                af[mi][0] = As[r * ASTRA + ka];
                af[mi][1] = As[(r + 8) * ASTRA + ka];
                af[mi][2] = As[r * ASTRA + ka + 4];
                af[mi][3] = As[(r + 8) * ASTRA + ka + 4];
            }
#pragma unroll
            for (int ni = 0; ni < 16; ni++) {
                int nr = wn * 128 + ni * 8 + g;
                uint32_t b0 = Bc[nr * BSTR + kb];
                uint32_t b1 = Bc[nr * BSTR + kb + 4];
                mma_tf32(acc[0][ni], af[0], b0, b1);
                mma_tf32(acc[1][ni], af[1], b0, b1);
            }
        }
    }

    // --- epilogue: fp16 messages ---
#pragma unroll
    for (int mi = 0; mi < 2; mi++) {
        int r0 = bm + wm * 32 + mi * 16 + g;
        int r1 = r0 + 8;
#pragma unroll
        for (int ni = 0; ni < 16; ni++) {
            int col = wn * 128 + ni * 8 + tig * 2;
            if (r0 < NNODES) {
                __half2 p = __float22half2_rn(make_float2(acc[mi][ni][0], acc[mi][ni][1]));
                *(unsigned*)&g_hw1h[(size_t)r0 * NHID + col] = *(unsigned*)&p;
            }
            if (r1 < NNODES) {
                __half2 p = __float22half2_rn(make_float2(acc[mi][ni][2], acc[mi][ni][3]));
                *(unsigned*)&g_hw1h[(size_t)r1 * NHID + col] = *(unsigned*)&p;
            }
        }
    }
}

// ---------------- agg layer 1 (fp16 messages, warp per node) -----------------
__global__ void agg1_kernel(const float* __restrict__ b1) {
    int gt   = blockIdx.x * blockDim.x + threadIdx.x;
    int node = gt >> 5;
    int lane = gt & 31;
    if (node >= NNODES) return;

    int beg = g_row_ptr[node], end = g_row_ptr[node + 1];
    float acc[8] = {0.f, 0.f, 0.f, 0.f, 0.f, 0.f, 0.f, 0.f};

    int e = beg;
    for (; e + 1 < end; e += 2) {
        int s0 = g_csr_src[e], s1 = g_csr_src[e + 1];
        float n0 = g_norm_s[s0], n1 = g_norm_s[s1];
        uint4 u0 = *(const uint4*)&g_hw1h[(size_t)s0 * NHID + lane * 8];
        uint4 u1 = *(const uint4*)&g_hw1h[(size_t)s1 * NHID + lane * 8];
        const unsigned* w0 = &u0.x;
        const unsigned* w1 = &u1.x;
#pragma unroll
        for (int j = 0; j < 4; j++) {
            float2 f0 = __half22float2(*(const __half2*)&w0[j]);
            float2 f1 = __half22float2(*(const __half2*)&w1[j]);
            acc[2 * j]     += f0.x * n0 + f1.x * n1;
            acc[2 * j + 1] += f0.y * n0 + f1.y * n1;
        }
    }
    if (e < end) {
        int s0 = g_csr_src[e];
        float n0 = g_norm_s[s0];
        uint4 u0 = *(const uint4*)&g_hw1h[(size_t)s0 * NHID + lane * 8];
        const unsigned* w0 = &u0.x;
#pragma unroll
        for (int j = 0; j < 4; j++) {
            float2 f0 = __half22float2(*(const __half2*)&w0[j]);
            acc[2 * j]     += f0.x * n0;
            acc[2 * j + 1] += f0.y * n0;
        }
    }

    float nd = g_norm_d[node];
    float* dst = &g_out1[(size_t)node * NHID + lane * 8];
    float4 bb0 = *(const float4*)&b1[lane * 8];
    float4 bb1 = *(const float4*)&b1[lane * 8 + 4];
    float4 o0, o1;
    o0.x = fmaxf(acc[0] * nd + bb0.x, 0.f);
    o0.y = fmaxf(acc[1] * nd + bb0.y, 0.f);
    o0.z = fmaxf(acc[2] * nd + bb0.z, 0.f);
    o0.w = fmaxf(acc[3] * nd + bb0.w, 0.f);
    o1.x = fmaxf(acc[4] * nd + bb1.x, 0.f);
    o1.y = fmaxf(acc[5] * nd + bb1.y, 0.f);
    o1.z = fmaxf(acc[6] * nd + bb1.z, 0.f);
    o1.w = fmaxf(acc[7] * nd + bb1.w, 0.f);
    *(float4*)&dst[0] = o0;
    *(float4*)&dst[4] = o1;
}

// ---------------- GEMM2: hws2h = fp16((out1 @ W2) * norm_s), f32x2 -----------
__global__ __launch_bounds__(256)
void gemm2_kernel(const float* __restrict__ W2) {
    __shared__ __align__(16) float Ws[NHID * NCLS];
    for (int i = threadIdx.x; i < (NHID * NCLS) / 4; i += blockDim.x)
        ((float4*)Ws)[i] = ((const float4*)W2)[i];
    __syncthreads();

    int row = blockIdx.x * blockDim.x + threadIdx.x;
    if (row >= NNODES) return;

    ull acc[NCLS / 2];
#pragma unroll
    for (int c = 0; c < NCLS / 2; c++) acc[c] = 0ull;

    const float* a = &g_out1[(size_t)row * NHID];
    for (int k0 = 0; k0 < NHID; k0 += 4) {
        float4 av = *(const float4*)&a[k0];
        float a4[4] = {av.x, av.y, av.z, av.w};
#pragma unroll
        for (int kk = 0; kk < 4; kk++) {
            ull ad = dup2(a4[kk]);
            const ull* w = (const ull*)&Ws[(k0 + kk) * NCLS];
#pragma unroll
            for (int c = 0; c < NCLS / 2; c++) acc[c] = ffma2(ad, w[c], acc[c]);
        }
    }
    float ns = g_norm_s[row];
    unsigned po[NCLS / 2];
#pragma unroll
    for (int c = 0; c < NCLS / 2; c++) {
        float lo, hi;
        unpack2(acc[c], lo, hi);
        __half2 p = __float22half2_rn(make_float2(lo * ns, hi * ns));
        po[c] = *(unsigned*)&p;
    }
    uint4* dst = (uint4*)&g_hws2h[(size_t)row * NCLS];
#pragma unroll
    for (int c = 0; c < NCLS / 8; c++)
        dst[c] = make_uint4(po[4 * c], po[4 * c + 1], po[4 * c + 2], po[4 * c + 3]);
}

// ---------------- agg layer 2 (fp16 messages) --------------------------------
__global__ void agg2_kernel(const float* __restrict__ b2, float* __restrict__ out) {
    int gt   = blockIdx.x * blockDim.x + threadIdx.x;
    int node = gt >> 5;
    int lane = gt & 31;
    if (node >= NNODES) return;

    int beg = g_row_ptr[node], end = g_row_ptr[node + 1];
    float2 acc = make_float2(0.f, 0.f);
    bool act = lane < (NCLS / 2);
    for (int e = beg; e < end; e++) {
        int s = g_csr_src[e];
        unsigned w = act ? *(const unsigned*)&g_hws2h[(size_t)s * NCLS + lane * 2] : 0u;
        float2 f = __half22float2(*(const __half2*)&w);
        acc.x += f.x; acc.y += f.y;
    }
    if (act) {
        float nd = g_norm_d[node];
        float2 bb = *(const float2*)&b2[lane * 2];
        *(float2*)&out[(size_t)node * NCLS + lane * 2] =
            make_float2(acc.x * nd + bb.x, acc.y * nd + bb.y);
    }
}

// ---------------- launch ------------------------------------------------------
static cudaStream_t g_s2 = 0;
static cudaEvent_t  g_ev_fork = 0, g_ev_w1 = 0, g_ev_join = 0;

extern "C" void kernel_launch(void* const* d_in, const int* in_sizes, int n_in,
                              void* d_out, int out_size) {
    const int*   feats = (const int*)d_in[0];
    const int*   src   = (const int*)d_in[1];
    const int*   dst   = (const int*)d_in[2];
    const float* emb   = (const float*)d_in[3];
    const float* W1    = (const float*)d_in[4];
    const float* b1    = (const float*)d_in[5];
    const float* W2    = (const float*)d_in[6];
    const float* b2    = (const float*)d_in[7];
    float*       out   = (float*)d_out;

    if (!g_s2) {
        cudaStreamCreateWithFlags(&g_s2, cudaStreamNonBlocking);
        cudaEventCreateWithFlags(&g_ev_fork, cudaEventDisableTiming);
        cudaEventCreateWithFlags(&g_ev_w1, cudaEventDisableTiming);
        cudaEventCreateWithFlags(&g_ev_join, cudaEventDisableTiming);
        cudaFuncSetAttribute(gemm1_fused_kernel,
                             cudaFuncAttributeMaxDynamicSharedMemorySize, G1_SMEM);
    }

    // fork side stream
    cudaEventRecord(g_ev_fork, 0);
    cudaStreamWaitEvent(g_s2, g_ev_fork, 0);

    // main: emb conversion -> fused embed+gemm1
    conv_emb_kernel<<<(NTOK * EMBD / 8 + 255) / 256, 256>>>(emb);

    // side: W1 prep + CSR chain (overlaps)
    prep_w1_kernel<<<256, 256, 0, g_s2>>>(W1);
    cudaEventRecord(g_ev_w1, g_s2);
    zero_degs_kernel<<<(NNODES + 511) / 512, 512, 0, g_s2>>>();
    degree_kernel<<<(NEDGES + 511) / 512, 512, 0, g_s2>>>(src, dst);
    scanA_kernel<<<NCHUNK, CHUNK, 0, g_s2>>>();
    scanB_kernel<<<1, 128, 0, g_s2>>>();
    scanC_kernel<<<NCHUNK, CHUNK, 0, g_s2>>>();
    csr_fill_kernel<<<(NEDGES + 511) / 512, 512, 0, g_s2>>>(src, dst);
    cudaEventRecord(g_ev_join, g_s2);

    // fused kernel needs emb table (main) + W1 tf32 image (s2)
    cudaStreamWaitEvent(0, g_ev_w1, 0);
    gemm1_fused_kernel<<<(NNODES + 127) / 128, 256, G1_SMEM>>>(feats);

    // agg1 needs CSR + norms
    cudaStreamWaitEvent(0, g_ev_join, 0);
    agg1_kernel<<<(NNODES * 32 + 255) / 256, 256>>>(b1);
    gemm2_kernel<<<(NNODES + 255) / 256, 256>>>(W2);
    agg2_kernel<<<(NNODES * 32 + 255) / 256, 256>>>(b2, out);
}

// round 9
// speedup vs baseline: 1.3828x; 1.3828x over previous
#include <cuda_runtime.h>
#include <cuda_fp16.h>
#include <math.h>
#include <stdint.h>

#define NNODES 50000
#define NEDGES 800000
#define NTOK   100000
#define SEQLEN 32
#define EMBD   128
#define INFEAT 256
#define NHID   256
#define NCLS   40

#define CHUNK   512
#define NCHUNK  98      // 98*512 = 50176 >= 50000

typedef unsigned long long ull;

// ---------------- scratch (device globals; no allocation allowed) ------------
__device__ int   g_deg_out[NNODES];
__device__ int   g_deg_in[NNODES];
__device__ float g_norm_s[NNODES];
__device__ float g_norm_d[NNODES];
__device__ int   g_row_ptr[NNODES + 1];
__device__ int   g_cursor[NNODES];
__device__ int   g_chunk_sum[NCHUNK];
__device__ int   g_chunk_off[NCHUNK];
__device__ int   g_csr_src[NEDGES];
__device__ float g_h[(size_t)NNODES * INFEAT];                    // pooled embeddings fp32
__device__ __align__(16) uint32_t g_w1t[NHID * INFEAT];           // W1^T [n][k] tf32 bits
__device__ __align__(16) __half g_hw1h[(size_t)NNODES * NHID];    // h@W1 fp16
__device__ __align__(16) __half g_out1h[(size_t)NNODES * NHID];   // relu(...) fp16
__device__ __align__(16) __half g_hws2h[(size_t)NNODES * NCLS];   // (out1@W2)*norm_s fp16

// ---------------- helpers -----------------------------------------------------
__device__ __forceinline__ ull ffma2(ull a, ull b, ull c) {
    ull d;
    asm("fma.rn.f32x2 %0, %1, %2, %3;" : "=l"(d) : "l"(a), "l"(b), "l"(c));
    return d;
}
__device__ __forceinline__ ull dup2(float x) {
    ull d;
    asm("mov.b64 %0, {%1, %1};" : "=l"(d) : "f"(x));
    return d;
}
__device__ __forceinline__ void unpack2(ull v, float& lo, float& hi) {
    asm("mov.b64 {%0, %1}, %2;" : "=f"(lo), "=f"(hi) : "l"(v));
}
__device__ __forceinline__ uint32_t f2tf32(float f) {
    uint32_t u;
    asm("cvt.rna.tf32.f32 %0, %1;" : "=r"(u) : "f"(f));
    return u;
}
__device__ __forceinline__ void mma_tf32(float* c, const uint32_t* a, uint32_t b0, uint32_t b1) {
    asm volatile(
        "mma.sync.aligned.m16n8k8.row.col.f32.tf32.tf32.f32 "
        "{%0,%1,%2,%3}, {%4,%5,%6,%7}, {%8,%9}, {%0,%1,%2,%3};"
        : "+f"(c[0]), "+f"(c[1]), "+f"(c[2]), "+f"(c[3])
        : "r"(a[0]), "r"(a[1]), "r"(a[2]), "r"(a[3]), "r"(b0), "r"(b1));
}

// ---------------- degree ------------------------------------------------------
__global__ void zero_degs_kernel() {
    int i = blockIdx.x * blockDim.x + threadIdx.x;
    if (i < NNODES) { g_deg_out[i] = 0; g_deg_in[i] = 0; }
}

__global__ void degree_kernel(const int* __restrict__ src, const int* __restrict__ dst) {
    int e = blockIdx.x * blockDim.x + threadIdx.x;
    if (e < NEDGES) {
        atomicAdd(&g_deg_out[src[e]], 1);
        atomicAdd(&g_deg_in[dst[e]], 1);
    }
}

// ---------------- scan + norms ------------------------------------------------
__global__ void scanA_kernel() {
    __shared__ int s[CHUNK];
    int t = threadIdx.x, b = blockIdx.x;
    int idx = b * CHUNK + t;
    int v = (idx < NNODES) ? g_deg_in[idx] : 0;
    s[t] = v;
    __syncthreads();
    for (int off = CHUNK / 2; off > 0; off >>= 1) {
        if (t < off) s[t] += s[t + off];
        __syncthreads();
    }
    if (t == 0) g_chunk_sum[b] = s[0];
}

__global__ void scanB_kernel() {
    __shared__ int s[128];
    int t = threadIdx.x;
    int v = (t < NCHUNK) ? g_chunk_sum[t] : 0;
    s[t] = v;
    __syncthreads();
    for (int off = 1; off < 128; off <<= 1) {
        int x = (t >= off) ? s[t - off] : 0;
        __syncthreads();
        s[t] += x;
        __syncthreads();
    }
    if (t < NCHUNK) g_chunk_off[t] = s[t] - v;
    if (t == 0) g_row_ptr[NNODES] = NEDGES;
}

__global__ void scanC_kernel() {
    __shared__ int s[CHUNK];
    int t = threadIdx.x, b = blockIdx.x;
    int idx = b * CHUNK + t;
    int v = (idx < NNODES) ? g_deg_in[idx] : 0;
    s[t] = v;
    __syncthreads();
    for (int off = 1; off < CHUNK; off <<= 1) {
        int x = (t >= off) ? s[t - off] : 0;
        __syncthreads();
        s[t] += x;
        __syncthreads();
    }
    if (idx < NNODES) {
        int excl = g_chunk_off[b] + s[t] - v;
        g_row_ptr[idx] = excl;
        g_cursor[idx]  = excl;
        int dins = v; if (dins < 1) dins = 1;
        int dofs = g_deg_out[idx]; if (dofs < 1) dofs = 1;
        g_norm_d[idx] = rsqrtf((float)dins);
        g_norm_s[idx] = rsqrtf((float)dofs);
    }
}

__global__ void csr_fill_kernel(const int* __restrict__ src, const int* __restrict__ dst) {
    int e = blockIdx.x * blockDim.x + threadIdx.x;
    if (e < NEDGES) {
        int d = dst[e];
        int pos = atomicAdd(&g_cursor[d], 1);
        g_csr_src[pos] = src[e];
    }
}

// ---------------- embedding pooling (warp per node, fp32 table) --------------
__global__ void embed_kernel(const int* __restrict__ feats, const float* __restrict__ emb) {
    int gt   = blockIdx.x * blockDim.x + threadIdx.x;
    int node = gt >> 5;
    int lane = gt & 31;
    if (node >= NNODES) return;

    int tok = feats[node * SEQLEN + lane];
    int cnt = __popc(__ballot_sync(0xffffffffu, tok != 0));
    if (cnt < 1) cnt = 1;

    float4 s  = make_float4(0.f, 0.f, 0.f, 0.f);
    float4 mx = make_float4(-INFINITY, -INFINITY, -INFINITY, -INFINITY);

#pragma unroll
    for (int t = 0; t < 32; t++) {
        int tk = __shfl_sync(0xffffffffu, tok, t);
        float4 v = make_float4(0.f, 0.f, 0.f, 0.f);
        if (tk != 0) v = *(const float4*)&emb[(size_t)tk * EMBD + lane * 4];
        s.x += v.x; s.y += v.y; s.z += v.z; s.w += v.w;
        mx.x = fmaxf(mx.x, v.x); mx.y = fmaxf(mx.y, v.y);
        mx.z = fmaxf(mx.z, v.z); mx.w = fmaxf(mx.w, v.w);
    }
    float inv = 1.0f / (float)cnt;
    float4 h1 = make_float4(s.x * inv, s.y * inv, s.z * inv, s.w * inv);
    size_t base = (size_t)node * INFEAT;
    *(float4*)&g_h[base + lane * 4]        = h1;
    *(float4*)&g_h[base + EMBD + lane * 4] = mx;
}

// ---------------- prep W1: [K][N] fp32 -> [N][K] tf32 bits -------------------
__global__ void prep_w1_kernel(const float* __restrict__ W1) {
    int i = blockIdx.x * blockDim.x + threadIdx.x;   // 65536
    int n = i >> 8, k = i & 255;
    g_w1t[n * INFEAT + k] = f2tf32(W1[k * NHID + n]);
}

// ---------------- GEMM1 via mma.sync tf32 ------------------------------------
#define KC 32
#define ASTR 36   // 32 + 4 pad words -> conflict-free fragment LDS

__global__ __launch_bounds__(256, 2)
void gemm1_mma_kernel() {
    extern __shared__ __align__(16) uint32_t smem[];
    uint32_t* As = smem;                    // [2][128][ASTR]
    uint32_t* Bs = smem + 2 * 128 * ASTR;   // [2][128][ASTR]

    int tid = threadIdx.x, wid = tid >> 5, lane = tid & 31;
    int wm = wid & 3, wn = wid >> 2;
    int g = lane >> 2, tig = lane & 3;
    int bm = blockIdx.x * 128, bn = blockIdx.y * 128;

    int lrow = tid >> 1, lhalf = (tid & 1) * 16;

    float acc[2][8][4];
#pragma unroll
    for (int mi = 0; mi < 2; mi++)
#pragma unroll
        for (int ni = 0; ni < 8; ni++)
#pragma unroll
            for (int q = 0; q < 4; q++) acc[mi][ni][q] = 0.f;

    float4 ar[4]; uint4 br[4];
    {
        int arow = bm + lrow;
#pragma unroll
        for (int q = 0; q < 4; q++) {
            ar[q] = make_float4(0.f, 0.f, 0.f, 0.f);
            if (arow < NNODES)
                ar[q] = *(const float4*)&g_h[(size_t)arow * INFEAT + lhalf + 4 * q];
            br[q] = *(const uint4*)&g_w1t[(bn + lrow) * INFEAT + lhalf + 4 * q];
        }
    }
#pragma unroll
    for (int q = 0; q < 4; q++) {
        uint32_t* a = &As[lrow * ASTR + lhalf + 4 * q];
        a[0] = f2tf32(ar[q].x); a[1] = f2tf32(ar[q].y);
        a[2] = f2tf32(ar[q].z); a[3] = f2tf32(ar[q].w);
        *(uint4*)&Bs[lrow * ASTR + lhalf + 4 * q] = br[q];
    }
    __syncthreads();

    const int NKC = INFEAT / KC;   // 8
    for (int kc = 0; kc < NKC; kc++) {
        int cur = kc & 1, nxt = cur ^ 1;
        if (kc + 1 < NKC) {
            int k0 = (kc + 1) * KC;
            int arow = bm + lrow;
#pragma unroll
            for (int q = 0; q < 4; q++) {
                ar[q] = make_float4(0.f, 0.f, 0.f, 0.f);
                if (arow < NNODES)
                    ar[q] = *(const float4*)&g_h[(size_t)arow * INFEAT + k0 + lhalf + 4 * q];
                br[q] = *(const uint4*)&g_w1t[(bn + lrow) * INFEAT + k0 + lhalf + 4 * q];
            }
        }

        const uint32_t* Ac = &As[cur * 128 * ASTR];
        const uint32_t* Bc = &Bs[cur * 128 * ASTR];
#pragma unroll
        for (int ks = 0; ks < 4; ks++) {
            int kb = ks * 8;
            uint32_t af[2][4];
#pragma unroll
            for (int mi = 0; mi < 2; mi++) {
                int r = wm * 32 + mi * 16 + g;
                af[mi][0] = Ac[r * ASTR + kb + tig];
                af[mi][1] = Ac[(r + 8) * ASTR + kb + tig];
                af[mi][2] = Ac[r * ASTR + kb + tig + 4];
                af[mi][3] = Ac[(r + 8) * ASTR + kb + tig + 4];
            }
#pragma unroll
            for (int ni = 0; ni < 8; ni++) {
                int nr = wn * 64 + ni * 8 + g;
                uint32_t b0 = Bc[nr * ASTR + kb + tig];
                uint32_t b1 = Bc[nr * ASTR + kb + tig + 4];
                mma_tf32(acc[0][ni], af[0], b0, b1);
                mma_tf32(acc[1][ni], af[1], b0, b1);
            }
        }

        if (kc + 1 < NKC) {
            __syncthreads();
#pragma unroll
            for (int q = 0; q < 4; q++) {
                uint32_t* a = &As[(nxt * 128 + lrow) * ASTR + lhalf + 4 * q];
                a[0] = f2tf32(ar[q].x); a[1] = f2tf32(ar[q].y);
                a[2] = f2tf32(ar[q].z); a[3] = f2tf32(ar[q].w);
                *(uint4*)&Bs[(nxt * 128 + lrow) * ASTR + lhalf + 4 * q] = br[q];
            }
            __syncthreads();
        }
    }

    // epilogue: fp16 store
#pragma unroll
    for (int mi = 0; mi < 2; mi++) {
        int r0 = bm + wm * 32 + mi * 16 + g;
        int r1 = r0 + 8;
#pragma unroll
        for (int ni = 0; ni < 8; ni++) {
            int col = bn + wn * 64 + ni * 8 + tig * 2;
            if (r0 < NNODES) {
                __half2 p = __float22half2_rn(make_float2(acc[mi][ni][0], acc[mi][ni][1]));
                *(unsigned*)&g_hw1h[(size_t)r0 * NHID + col] = *(unsigned*)&p;
            }
            if (r1 < NNODES) {
                __half2 p = __float22half2_rn(make_float2(acc[mi][ni][2], acc[mi][ni][3]));
                *(unsigned*)&g_hw1h[(size_t)r1 * NHID + col] = *(unsigned*)&p;
            }
        }
    }
}
#define G1_SMEM (4 * 128 * ASTR * 4)   // 73728 bytes

// ---------------- agg layer 1 (fp16 messages, fp16 out) ----------------------
__global__ void agg1_kernel(const float* __restrict__ b1) {
    int gt   = blockIdx.x * blockDim.x + threadIdx.x;
    int node = gt >> 5;
    int lane = gt & 31;
    if (node >= NNODES) return;

    int beg = g_row_ptr[node], end = g_row_ptr[node + 1];
    float acc[8] = {0.f, 0.f, 0.f, 0.f, 0.f, 0.f, 0.f, 0.f};

    int e = beg;
    for (; e + 1 < end; e += 2) {
        int s0 = g_csr_src[e], s1 = g_csr_src[e + 1];
        float n0 = g_norm_s[s0], n1 = g_norm_s[s1];
        uint4 u0 = *(const uint4*)&g_hw1h[(size_t)s0 * NHID + lane * 8];
        uint4 u1 = *(const uint4*)&g_hw1h[(size_t)s1 * NHID + lane * 8];
        const unsigned* w0 = &u0.x;
        const unsigned* w1 = &u1.x;
#pragma unroll
        for (int j = 0; j < 4; j++) {
            float2 f0 = __half22float2(*(const __half2*)&w0[j]);
            float2 f1 = __half22float2(*(const __half2*)&w1[j]);
            acc[2 * j]     += f0.x * n0 + f1.x * n1;
            acc[2 * j + 1] += f0.y * n0 + f1.y * n1;
        }
    }
    if (e < end) {
        int s0 = g_csr_src[e];
        float n0 = g_norm_s[s0];
        uint4 u0 = *(const uint4*)&g_hw1h[(size_t)s0 * NHID + lane * 8];
        const unsigned* w0 = &u0.x;
#pragma unroll
        for (int j = 0; j < 4; j++) {
            float2 f0 = __half22float2(*(const __half2*)&w0[j]);
            acc[2 * j]     += f0.x * n0;
            acc[2 * j + 1] += f0.y * n0;
        }
    }

    float nd = g_norm_d[node];
    float4 bb0 = *(const float4*)&b1[lane * 8];
    float4 bb1 = *(const float4*)&b1[lane * 8 + 4];
    float o[8];
    o[0] = fmaxf(acc[0] * nd + bb0.x, 0.f);
    o[1] = fmaxf(acc[1] * nd + bb0.y, 0.f);
    o[2] = fmaxf(acc[2] * nd + bb0.z, 0.f);
    o[3] = fmaxf(acc[3] * nd + bb0.w, 0.f);
    o[4] = fmaxf(acc[4] * nd + bb1.x, 0.f);
    o[5] = fmaxf(acc[5] * nd + bb1.y, 0.f);
    o[6] = fmaxf(acc[6] * nd + bb1.z, 0.f);
    o[7] = fmaxf(acc[7] * nd + bb1.w, 0.f);
    __half2 p0 = __float22half2_rn(make_float2(o[0], o[1]));
    __half2 p1 = __float22half2_rn(make_float2(o[2], o[3]));
    __half2 p2 = __float22half2_rn(make_float2(o[4], o[5]));
    __half2 p3 = __float22half2_rn(make_float2(o[6], o[7]));
    *(uint4*)&g_out1h[(size_t)node * NHID + lane * 8] =
        make_uint4(*(unsigned*)&p0, *(unsigned*)&p1, *(unsigned*)&p2, *(unsigned*)&p3);
}

// ---------------- GEMM2: hws2h = fp16((out1 @ W2) * norm_s), f32x2 -----------
__global__ __launch_bounds__(256)
void gemm2_kernel(const float* __restrict__ W2) {
    __shared__ __align__(16) float Ws[NHID * NCLS];
    for (int i = threadIdx.x; i < (NHID * NCLS) / 4; i += blockDim.x)
        ((float4*)Ws)[i] = ((const float4*)W2)[i];
    __syncthreads();

    int row = blockIdx.x * blockDim.x + threadIdx.x;
    if (row >= NNODES) return;

    ull acc[NCLS / 2];
#pragma unroll
    for (int c = 0; c < NCLS / 2; c++) acc[c] = 0ull;

    const __half* a = &g_out1h[(size_t)row * NHID];
    for (int k0 = 0; k0 < NHID; k0 += 8) {
        uint4 u = *(const uint4*)&a[k0];
        const unsigned* uw = &u.x;
        float a8[8];
#pragma unroll
        for (int j = 0; j < 4; j++) {
            float2 f = __half22float2(*(const __half2*)&uw[j]);
            a8[2 * j] = f.x; a8[2 * j + 1] = f.y;
        }
#pragma unroll
        for (int kk = 0; kk < 8; kk++) {
            ull ad = dup2(a8[kk]);
            const ull* w = (const ull*)&Ws[(k0 + kk) * NCLS];
#pragma unroll
            for (int c = 0; c < NCLS / 2; c++) acc[c] = ffma2(ad, w[c], acc[c]);
        }
    }
    float ns = g_norm_s[row];
    unsigned po[NCLS / 2];
#pragma unroll
    for (int c = 0; c < NCLS / 2; c++) {
        float lo, hi;
        unpack2(acc[c], lo, hi);
        __half2 p = __float22half2_rn(make_float2(lo * ns, hi * ns));
        po[c] = *(unsigned*)&p;
    }
    uint4* dst = (uint4*)&g_hws2h[(size_t)row * NCLS];
#pragma unroll
    for (int c = 0; c < NCLS / 8; c++)
        dst[c] = make_uint4(po[4 * c], po[4 * c + 1], po[4 * c + 2], po[4 * c + 3]);
}

// ---------------- agg layer 2 (fp16 messages) --------------------------------
__global__ void agg2_kernel(const float* __restrict__ b2, float* __restrict__ out) {
    int gt   = blockIdx.x * blockDim.x + threadIdx.x;
    int node = gt >> 5;
    int lane = gt & 31;
    if (node >= NNODES) return;

    int beg = g_row_ptr[node], end = g_row_ptr[node + 1];
    float2 acc = make_float2(0.f, 0.f);
    bool act = lane < (NCLS / 2);
    for (int e = beg; e < end; e++) {
        int s = g_csr_src[e];
        unsigned w = act ? *(const unsigned*)&g_hws2h[(size_t)s * NCLS + lane * 2] : 0u;
        float2 f = __half22float2(*(const __half2*)&w);
        acc.x += f.x; acc.y += f.y;
    }
    if (act) {
        float nd = g_norm_d[node];
        float2 bb = *(const float2*)&b2[lane * 2];
        *(float2*)&out[(size_t)node * NCLS + lane * 2] =
            make_float2(acc.x * nd + bb.x, acc.y * nd + bb.y);
    }
}

// ---------------- launch ------------------------------------------------------
static cudaStream_t g_s2 = 0;
static cudaEvent_t  g_ev_fork = 0, g_ev_w1 = 0, g_ev_join = 0;

extern "C" void kernel_launch(void* const* d_in, const int* in_sizes, int n_in,
                              void* d_out, int out_size) {
    const int*   feats = (const int*)d_in[0];
    const int*   src   = (const int*)d_in[1];
    const int*   dst   = (const int*)d_in[2];
    const float* emb   = (const float*)d_in[3];
    const float* W1    = (const float*)d_in[4];
    const float* b1    = (const float*)d_in[5];
    const float* W2    = (const float*)d_in[6];
    const float* b2    = (const float*)d_in[7];
    float*       out   = (float*)d_out;

    if (!g_s2) {
        cudaStreamCreateWithFlags(&g_s2, cudaStreamNonBlocking);
        cudaEventCreateWithFlags(&g_ev_fork, cudaEventDisableTiming);
        cudaEventCreateWithFlags(&g_ev_w1, cudaEventDisableTiming);
        cudaEventCreateWithFlags(&g_ev_join, cudaEventDisableTiming);
        cudaFuncSetAttribute(gemm1_mma_kernel,
                             cudaFuncAttributeMaxDynamicSharedMemorySize, G1_SMEM);
    }

    // fork side stream
    cudaEventRecord(g_ev_fork, 0);
    cudaStreamWaitEvent(g_s2, g_ev_fork, 0);

    // submission order chosen so gemm1 is launch idx 3 (ncu profiles idx 3):
    embed_kernel<<<(NNODES * 32 + 255) / 256, 256>>>(feats, emb);          // 0 main
    prep_w1_kernel<<<256, 256, 0, g_s2>>>(W1);                             // 1 s2
    cudaEventRecord(g_ev_w1, g_s2);
    zero_degs_kernel<<<(NNODES + 511) / 512, 512, 0, g_s2>>>();            // 2 s2
    cudaStreamWaitEvent(0, g_ev_w1, 0);
    gemm1_mma_kernel<<<dim3((NNODES + 127) / 128, 2), 256, G1_SMEM>>>();   // 3 main
    degree_kernel<<<(NEDGES + 511) / 512, 512, 0, g_s2>>>(src, dst);       // 4 s2
    scanA_kernel<<<NCHUNK, CHUNK, 0, g_s2>>>();                            // 5 s2
    scanB_kernel<<<1, 128, 0, g_s2>>>();                                   // 6 s2
    scanC_kernel<<<NCHUNK, CHUNK, 0, g_s2>>>();                            // 7 s2
    csr_fill_kernel<<<(NEDGES + 511) / 512, 512, 0, g_s2>>>(src, dst);     // 8 s2
    cudaEventRecord(g_ev_join, g_s2);

    // agg1 needs CSR + norms (s2) and gemm1 (main)
    cudaStreamWaitEvent(0, g_ev_join, 0);
    agg1_kernel<<<(NNODES * 32 + 255) / 256, 256>>>(b1);
    gemm2_kernel<<<(NNODES + 255) / 256, 256>>>(W2);
    agg2_kernel<<<(NNODES * 32 + 255) / 256, 256>>>(b2, out);
}